// round 2
// baseline (speedup 1.0000x reference)
#include <cuda_runtime.h>
#include <cuda_bf16.h>
#include <cstdint>

// Problem constants (fixed by the reference).
#define NNODES 50000
#define NEDGES 800000
#define DFEAT  128

// ---------------------------------------------------------------------------
// Scratch (no allocations allowed -> __device__ globals).
// __align__(16) guarantees the float4 / red.v4 paths are legal.
// ---------------------------------------------------------------------------
__device__ __align__(16) float g_agg[NNODES * DFEAT];   // 25.6 MB aggregation
__device__ __align__(16) float g_h0[NNODES * DFEAT];    // layer-1 output
__device__ __align__(16) float g_h1[NNODES * DFEAT];    // layer-2 output
__device__ float g_invdeg[NNODES];
__device__ int   g_deg[NNODES];

// ---------------------------------------------------------------------------
// Small utility kernels
// ---------------------------------------------------------------------------
__global__ void k_zero_deg() {
    int i = blockIdx.x * blockDim.x + threadIdx.x;
    if (i < NNODES) g_deg[i] = 0;
}

// edge_index is int32 (JAX default x64-disabled downgrades int64 -> int32).
__global__ void k_count_deg(const int* __restrict__ ei) {
    int e = blockIdx.x * blockDim.x + threadIdx.x;
    if (e < NEDGES) {
        int dst = ei[NEDGES + e];
        atomicAdd(&g_deg[dst], 1);
    }
}

__global__ void k_invdeg() {
    int i = blockIdx.x * blockDim.x + threadIdx.x;
    if (i < NNODES) g_invdeg[i] = 1.0f / fmaxf((float)g_deg[i], 1.0f);
}

__global__ void k_zero_agg() {
    int i = blockIdx.x * blockDim.x + threadIdx.x;   // float4 index
    if (i < (NNODES * DFEAT) / 4)
        ((float4*)g_agg)[i] = make_float4(0.f, 0.f, 0.f, 0.f);
}

// ---------------------------------------------------------------------------
// Edge scatter: one warp per edge, 4 floats per lane, vector red (sm_90+).
// agg[dst] += in[src]
// ---------------------------------------------------------------------------
__global__ void k_scatter(const float* __restrict__ in,
                          const int* __restrict__ ei) {
    int t = blockIdx.x * blockDim.x + threadIdx.x;
    int e = t >> 5;
    int lane = t & 31;
    if (e >= NEDGES) return;
    int src = ei[e];
    int dst = ei[NEDGES + e];
    float4 v = *(const float4*)(in + (size_t)src * DFEAT + lane * 4);
    float* p = g_agg + (size_t)dst * DFEAT + lane * 4;
    asm volatile("red.global.add.v4.f32 [%0], {%1, %2, %3, %4};"
                 :: "l"(p), "f"(v.x), "f"(v.y), "f"(v.z), "f"(v.w)
                 : "memory");
}

// ---------------------------------------------------------------------------
// Fused GEMM: out = act( X @ Wl + (g_agg * invdeg) @ Wr + bias )
// Treated as one K=256 GEMM: k<128 reads (X, Wl), k>=128 reads (agg, Wr).
// Tile: TM=64 rows x TN cols, TK=32, 256 threads.
//   TN=128 -> micro-tile 8x4 ; TN=64 -> micro-tile 4x4.
// ---------------------------------------------------------------------------
template<int TN, int MR, bool RELU>
__global__ void __launch_bounds__(256)
k_gemm(const float* __restrict__ X,
       const float* __restrict__ Wl,
       const float* __restrict__ Wr,
       const float* __restrict__ bias,
       float* __restrict__ out, int nRows) {
    constexpr int TM = 64;
    constexpr int TK = 32;
    static_assert((TN / 4) * (TM / MR) == 256, "thread count");

    __shared__ __align__(16) float As[TK][TM];
    __shared__ __align__(16) float Bs[TK][TN];

    const int tid = threadIdx.x;
    const int tx = tid % (TN / 4);     // column group (4 cols)
    const int ty = tid / (TN / 4);     // row group (MR rows)
    const int row0 = blockIdx.x * TM;

    float4 acc[MR];
#pragma unroll
    for (int r = 0; r < MR; ++r) acc[r] = make_float4(0.f, 0.f, 0.f, 0.f);

#pragma unroll
    for (int kb = 0; kb < 8; ++kb) {
        const bool fromAgg = (kb >= 4);
        const int kloc = (kb & 3) * TK;            // 0..96 within the 128-wide half
        const float* asrc = fromAgg ? g_agg : X;
        const float* wsrc = fromAgg ? Wr : Wl;

        // --- load A tile: 64 rows x 32 k = 512 float4, 2 per thread ---
#pragma unroll
        for (int it = 0; it < 2; ++it) {
            int idx = tid + it * 256;
            int m = idx >> 3;                      // 0..63
            int k4 = (idx & 7) << 2;               // 0,4,...,28
            int row = row0 + m;
            float4 v = make_float4(0.f, 0.f, 0.f, 0.f);
            if (row < nRows) {
                v = *(const float4*)(asrc + (size_t)row * DFEAT + kloc + k4);
                if (fromAgg) {
                    float s = g_invdeg[row];
                    v.x *= s; v.y *= s; v.z *= s; v.w *= s;
                }
            }
            As[k4 + 0][m] = v.x;
            As[k4 + 1][m] = v.y;
            As[k4 + 2][m] = v.z;
            As[k4 + 3][m] = v.w;
        }

        // --- load B tile: TK x TN floats ---
        constexpr int BV = (TK * TN / 4) / 256;    // 4 for TN=128, 2 for TN=64
#pragma unroll
        for (int it = 0; it < BV; ++it) {
            int idx = tid + it * 256;
            int n4 = idx % (TN / 4);
            int kk = idx / (TN / 4);
            *(float4*)&Bs[kk][n4 * 4] =
                *(const float4*)(wsrc + (size_t)(kloc + kk) * TN + n4 * 4);
        }
        __syncthreads();

        // --- compute ---
#pragma unroll
        for (int kk = 0; kk < TK; ++kk) {
            float4 bv = *(const float4*)&Bs[kk][tx * 4];
            float a[MR];
#pragma unroll
            for (int r = 0; r < MR; r += 4) {
                float4 av = *(const float4*)&As[kk][ty * MR + r];
                a[r] = av.x; a[r + 1] = av.y; a[r + 2] = av.z; a[r + 3] = av.w;
            }
#pragma unroll
            for (int r = 0; r < MR; ++r) {
                acc[r].x += a[r] * bv.x;
                acc[r].y += a[r] * bv.y;
                acc[r].z += a[r] * bv.z;
                acc[r].w += a[r] * bv.w;
            }
        }
        __syncthreads();
    }

    // --- epilogue ---
    float4 bv = *(const float4*)(bias + tx * 4);
#pragma unroll
    for (int r = 0; r < MR; ++r) {
        int row = row0 + ty * MR + r;
        if (row < nRows) {
            float4 v = acc[r];
            v.x += bv.x; v.y += bv.y; v.z += bv.z; v.w += bv.w;
            if (RELU) {
                v.x = fmaxf(v.x, 0.f); v.y = fmaxf(v.y, 0.f);
                v.z = fmaxf(v.z, 0.f); v.w = fmaxf(v.w, 0.f);
            }
            *(float4*)(out + (size_t)row * TN + tx * 4) = v;
        }
    }
}

// ---------------------------------------------------------------------------
// Launch
// ---------------------------------------------------------------------------
extern "C" void kernel_launch(void* const* d_in, const int* in_sizes, int n_in,
                              void* d_out, int out_size) {
    const float* x   = (const float*)d_in[0];
    const int*   ei  = (const int*)d_in[1];      // int32 (JAX x64 disabled)
    const float* Wl1 = (const float*)d_in[2];
    const float* Wr1 = (const float*)d_in[3];
    const float* b1  = (const float*)d_in[4];
    const float* Wl2 = (const float*)d_in[5];
    const float* Wr2 = (const float*)d_in[6];
    const float* b2  = (const float*)d_in[7];
    const float* Wl3 = (const float*)d_in[8];
    const float* Wr3 = (const float*)d_in[9];
    const float* b3  = (const float*)d_in[10];
    float* out = (float*)d_out;

    float* h0 = nullptr;
    float* h1 = nullptr;
    cudaGetSymbolAddress((void**)&h0, g_h0);
    cudaGetSymbolAddress((void**)&h1, g_h1);

    const int ZB = 256;
    const int nodeBlocks = (NNODES + ZB - 1) / ZB;               // 196
    const int edgeBlocks = (NEDGES + ZB - 1) / ZB;               // 3125
    const int aggBlocks  = ((NNODES * DFEAT) / 4 + ZB - 1) / ZB; // 6250
    const int scatBlocks = (NEDGES * 32) / ZB;                   // 100000
    const int gemmBlocks = (NNODES + 63) / 64;                   // 782

    // Degree (recomputed every call; deterministic)
    k_zero_deg<<<nodeBlocks, ZB>>>();
    k_count_deg<<<edgeBlocks, ZB>>>(ei);
    k_invdeg<<<nodeBlocks, ZB>>>();

    // Layer 1: x -> h0 (relu)
    k_zero_agg<<<aggBlocks, ZB>>>();
    k_scatter<<<scatBlocks, ZB>>>(x, ei);
    k_gemm<128, 8, true><<<gemmBlocks, ZB>>>(x, Wl1, Wr1, b1, h0, NNODES);

    // Layer 2: h0 -> h1 (relu)
    k_zero_agg<<<aggBlocks, ZB>>>();
    k_scatter<<<scatBlocks, ZB>>>(h0, ei);
    k_gemm<128, 8, true><<<gemmBlocks, ZB>>>(h0, Wl2, Wr2, b2, h1, NNODES);

    // Layer 3: h1 -> out (no activation, TN=64)
    k_zero_agg<<<aggBlocks, ZB>>>();
    k_scatter<<<scatBlocks, ZB>>>(h1, ei);
    k_gemm<64, 4, false><<<gemmBlocks, ZB>>>(h1, Wl3, Wr3, b3, out, NNODES);
}